// round 1
// baseline (speedup 1.0000x reference)
#include <cuda_runtime.h>
#include <math.h>

#define S_  256
#define I_  512
#define CM  64
#define CZ  128
#define H_  8
#define CH  32
#define HC  256
#define NN  (S_*CH)   // 8192
#define EPS 1e-5f

// ---- scratch (static device globals; no allocation allowed) ----
__device__ float d_mln[(size_t)S_*I_*CM];     // 32 MB  LN(m)
__device__ float d_vbuf[(size_t)H_*I_*S_*CH]; // 128 MB v in [h][j][s][c]
__device__ float d_gbuf[(size_t)S_*I_*HC];    // 128 MB sigmoid(g) in [s][i][hc]
__device__ float d_bw[(size_t)H_*I_*I_];      // 8 MB   b then w in [h][i][j]
__device__ float d_obuf[(size_t)H_*I_*NN];    // 128 MB o in [h][i][s*32+c]

__device__ __forceinline__ float warp_sum(float v) {
#pragma unroll
    for (int o = 16; o; o >>= 1) v += __shfl_xor_sync(0xffffffffu, v, o);
    return v;
}
__device__ __forceinline__ float warp_max(float v) {
#pragma unroll
    for (int o = 16; o; o >>= 1) v = fmaxf(v, __shfl_xor_sync(0xffffffffu, v, o));
    return v;
}

// ---------------- K1: LayerNorm(m) -> d_mln.  warp per row of 64 ----------------
__global__ void k_ln_m(const float* __restrict__ m, const float* __restrict__ g,
                       const float* __restrict__ b) {
    int row  = blockIdx.x * 8 + (threadIdx.x >> 5);
    int lane = threadIdx.x & 31;
    const float* x = m + (size_t)row * CM;
    float v0 = x[lane], v1 = x[lane + 32];
    float mu = warp_sum(v0 + v1) * (1.f / 64.f);
    float d0 = v0 - mu, d1 = v1 - mu;
    float var = warp_sum(d0 * d0 + d1 * d1) * (1.f / 64.f);
    float rs = rsqrtf(var + EPS);
    float* y = d_mln + (size_t)row * CM;
    y[lane]      = d0 * rs * g[lane]      + b[lane];
    y[lane + 32] = d1 * rs * g[lane + 32] + b[lane + 32];
}

// ------- K2: [131072 x 64] @ [64 x 256] for v (MODE 0) / g (MODE 1) -------
// block = 256 threads, 32 rows x 256 cols, W transposed in smem, reg tile 8x4.
template <int MODE>
__global__ void __launch_bounds__(256) k_vg(const float* __restrict__ W,
                                            const float* __restrict__ msk) {
    extern __shared__ float sm[];
    float* Ws = sm;                 // [64][260]  Ws[k*260+col]
    float* mT = sm + 64 * 260;      // [64][36]   mT[k*36+r]
    int t = threadIdx.x;
#pragma unroll
    for (int q = 0; q < 64; q++) {
        int idx = q * 256 + t;
        int col = idx >> 6, k = idx & 63;
        Ws[k * 260 + col] = W[idx];
    }
    int rowBase = blockIdx.x * 32;
#pragma unroll
    for (int q = 0; q < 8; q++) {
        int idx = q * 256 + t;
        int r = idx >> 6, k = idx & 63;
        mT[k * 36 + r] = d_mln[(size_t)(rowBase + r) * CM + k];
    }
    __syncthreads();
    int tx = t & 63, ty = t >> 6;
    float acc[8][4];
#pragma unroll
    for (int r = 0; r < 8; r++)
#pragma unroll
        for (int c = 0; c < 4; c++) acc[r][c] = 0.f;

    const float* wsp = Ws + tx * 4;
    const float* mtp = mT + ty * 8;
#pragma unroll 8
    for (int k = 0; k < 64; k++) {
        float4 w4 = *(const float4*)(wsp + k * 260);
#pragma unroll
        for (int r = 0; r < 8; r++) {
            float mv = mtp[k * 36 + r];
            acc[r][0] += mv * w4.x;
            acc[r][1] += mv * w4.y;
            acc[r][2] += mv * w4.z;
            acc[r][3] += mv * w4.w;
        }
    }
#pragma unroll
    for (int r = 0; r < 8; r++) {
        int gr = rowBase + ty * 8 + r;
        if (MODE == 0) {
            int s = gr >> 9, j = gr & 511;
            float mk = msk[gr];
            int col0 = tx * 4;
            int h = col0 >> 5, cc = col0 & 31;
            float4 o4 = make_float4(acc[r][0] * mk, acc[r][1] * mk,
                                    acc[r][2] * mk, acc[r][3] * mk);
            *(float4*)(d_vbuf + (((size_t)h * I_ + j) * S_ + s) * CH + cc) = o4;
        } else {
            float4 o4;
            o4.x = 1.f / (1.f + __expf(-acc[r][0]));
            o4.y = 1.f / (1.f + __expf(-acc[r][1]));
            o4.z = 1.f / (1.f + __expf(-acc[r][2]));
            o4.w = 1.f / (1.f + __expf(-acc[r][3]));
            *(float4*)(d_gbuf + (size_t)gr * HC + tx * 4) = o4;
        }
    }
}

// ---- K3: b[h][i][j] = LN(z[i][j]) . W_b[h] + INF*(zmask-1).  warp per (i,j) ----
__global__ void k_b(const float* __restrict__ z, const float* __restrict__ zg,
                    const float* __restrict__ zb, const float* __restrict__ Wb,
                    const float* __restrict__ zmask) {
    __shared__ float Wbs[H_ * CZ];
    __shared__ float zgs[CZ], zbs[CZ];
    int t = threadIdx.x;
    for (int idx = t; idx < H_ * CZ; idx += 256) Wbs[idx] = Wb[idx];
    if (t < CZ) { zgs[t] = zg[t]; zbs[t] = zb[t]; }
    __syncthreads();

    int w = blockIdx.x * 8 + (t >> 5);
    int lane = t & 31;
    const float4 zv = *(const float4*)(z + (size_t)w * CZ + lane * 4);
    float mu = warp_sum(zv.x + zv.y + zv.z + zv.w) * (1.f / 128.f);
    float e0 = zv.x - mu, e1 = zv.y - mu, e2 = zv.z - mu, e3 = zv.w - mu;
    float var = warp_sum(e0 * e0 + e1 * e1 + e2 * e2 + e3 * e3) * (1.f / 128.f);
    float rs = rsqrtf(var + EPS);
    int k0 = lane * 4;
    float l0 = e0 * rs * zgs[k0]     + zbs[k0];
    float l1 = e1 * rs * zgs[k0 + 1] + zbs[k0 + 1];
    float l2 = e2 * rs * zgs[k0 + 2] + zbs[k0 + 2];
    float l3 = e3 * rs * zgs[k0 + 3] + zbs[k0 + 3];
    float myval = 0.f;
#pragma unroll
    for (int h = 0; h < 8; h++) {
        float4 w4 = *(const float4*)(Wbs + h * CZ + k0);
        float a = l0 * w4.x + l1 * w4.y + l2 * w4.z + l3 * w4.w;
        a = warp_sum(a);
        if (lane == h) myval = a;
    }
    if (lane < 8) {
        int i = w >> 9, j = w & 511;
        d_bw[((size_t)lane * I_ + i) * I_ + j] = myval + 1e8f * (zmask[w] - 1.f);
    }
}

// ---------------- K4: softmax over j (row length 512), warp per (h,i) ----------------
__global__ void k_softmax() {
    int row  = blockIdx.x * 8 + (threadIdx.x >> 5);  // H_*I_ rows
    int lane = threadIdx.x & 31;
    float* p = d_bw + (size_t)row * I_;
    float4 x[4];
#pragma unroll
    for (int q = 0; q < 4; q++) x[q] = *(float4*)(p + q * 128 + lane * 4);
    float mx = -3.4e38f;
#pragma unroll
    for (int q = 0; q < 4; q++)
        mx = fmaxf(mx, fmaxf(fmaxf(x[q].x, x[q].y), fmaxf(x[q].z, x[q].w)));
    mx = warp_max(mx);
    float sum = 0.f;
#pragma unroll
    for (int q = 0; q < 4; q++) {
        x[q].x = __expf(x[q].x - mx); x[q].y = __expf(x[q].y - mx);
        x[q].z = __expf(x[q].z - mx); x[q].w = __expf(x[q].w - mx);
        sum += x[q].x + x[q].y + x[q].z + x[q].w;
    }
    sum = warp_sum(sum);
    float inv = 1.f / sum;
#pragma unroll
    for (int q = 0; q < 4; q++) {
        x[q].x *= inv; x[q].y *= inv; x[q].z *= inv; x[q].w *= inv;
        *(float4*)(p + q * 128 + lane * 4) = x[q];
    }
}

// ---- K5: einsum as batched SGEMM. Per head: O[i][n] = W[i][j] @ V[j][n],
//      M=512, N=8192, K=512.  128x128x8 tiles, 8x8 per thread. ----
__global__ void __launch_bounds__(256) k_einsum() {
    __shared__ __align__(16) float As[8][128];
    __shared__ __align__(16) float Bs[8][128];
    int h = blockIdx.z;
    const float* A = d_bw   + (size_t)h * I_ * I_;
    const float* B = d_vbuf + (size_t)h * I_ * NN;
    float*       C = d_obuf + (size_t)h * I_ * NN;
    int mBase = blockIdx.y * 128, nBase = blockIdx.x * 128;
    int t = threadIdx.x;
    int am = t >> 1, aq = (t & 1) * 4;
    int bk = t >> 5, bn = (t & 31) * 4;
    int tm = (t >> 4) * 8, tn = (t & 15) * 8;

    float acc[8][8];
#pragma unroll
    for (int r = 0; r < 8; r++)
#pragma unroll
        for (int c = 0; c < 8; c++) acc[r][c] = 0.f;

    const float* Aptr = A + (size_t)(mBase + am) * I_ + aq;
    const float* Bptr = B + (size_t)bk * NN + nBase + bn;

    for (int k0 = 0; k0 < I_; k0 += 8) {
        float4 a4 = *(const float4*)(Aptr + k0);
        float4 b4 = *(const float4*)(Bptr + (size_t)k0 * NN);
        __syncthreads();
        As[aq + 0][am] = a4.x;
        As[aq + 1][am] = a4.y;
        As[aq + 2][am] = a4.z;
        As[aq + 3][am] = a4.w;
        *(float4*)&Bs[bk][bn] = b4;
        __syncthreads();
#pragma unroll
        for (int kk = 0; kk < 8; kk++) {
            float a[8], b[8];
            *(float4*)(a)     = *(const float4*)&As[kk][tm];
            *(float4*)(a + 4) = *(const float4*)&As[kk][tm + 4];
            *(float4*)(b)     = *(const float4*)&Bs[kk][tn];
            *(float4*)(b + 4) = *(const float4*)&Bs[kk][tn + 4];
#pragma unroll
            for (int r = 0; r < 8; r++)
#pragma unroll
                for (int c = 0; c < 8; c++) acc[r][c] += a[r] * b[c];
        }
    }
#pragma unroll
    for (int r = 0; r < 8; r++) {
        float* Cr = C + (size_t)(mBase + tm + r) * NN + nBase + tn;
        *(float4*)(Cr)     = make_float4(acc[r][0], acc[r][1], acc[r][2], acc[r][3]);
        *(float4*)(Cr + 4) = make_float4(acc[r][4], acc[r][5], acc[r][6], acc[r][7]);
    }
}

// ---- K6: out[row][cm] = (g[row][:] * o_gather[row][:]) @ W_o[cm][:]
//      64 rows/block, K=256, 64 cols. ----
__global__ void __launch_bounds__(256) k_out(const float* __restrict__ Wo,
                                             float* __restrict__ out) {
    extern __shared__ float sm[];
    float* WoT = sm;              // [256][68]  WoT[k*68+cm]
    float* aT  = sm + 256 * 68;   // [256][66]  aT[k*66+r]
    int t = threadIdx.x;
#pragma unroll 4
    for (int q = 0; q < 64; q++) {
        int idx = q * 256 + t;
        int cm = idx >> 8, k = idx & 255;
        WoT[k * 68 + cm] = Wo[idx];
    }
    int rowBase = blockIdx.x * 64;
#pragma unroll 4
    for (int q = 0; q < 64; q++) {
        int idx = q * 256 + t;
        int r = idx >> 8, kk = idx & 255;
        int gr = rowBase + r;
        int s = gr >> 9, i = gr & 511;
        int h = kk >> 5, c = kk & 31;
        float gv = d_gbuf[(size_t)gr * HC + kk];
        float ov = d_obuf[((size_t)h * I_ + i) * NN + s * CH + c];
        aT[kk * 66 + r] = gv * ov;
    }
    __syncthreads();
    int tx = t & 15, ty = t >> 4;
    float acc[4][4];
#pragma unroll
    for (int r = 0; r < 4; r++)
#pragma unroll
        for (int c = 0; c < 4; c++) acc[r][c] = 0.f;

#pragma unroll 4
    for (int k = 0; k < 256; k++) {
        float4 w4 = *(const float4*)(WoT + k * 68 + tx * 4);
#pragma unroll
        for (int r = 0; r < 4; r++) {
            float a = aT[k * 66 + ty * 4 + r];
            acc[r][0] += a * w4.x;
            acc[r][1] += a * w4.y;
            acc[r][2] += a * w4.z;
            acc[r][3] += a * w4.w;
        }
    }
#pragma unroll
    for (int r = 0; r < 4; r++) {
        *(float4*)(out + (size_t)(rowBase + ty * 4 + r) * CM + tx * 4) =
            make_float4(acc[r][0], acc[r][1], acc[r][2], acc[r][3]);
    }
}

extern "C" void kernel_launch(void* const* d_in, const int* in_sizes, int n_in,
                              void* d_out, int out_size) {
    const float* m        = (const float*)d_in[0];
    const float* z        = (const float*)d_in[1];
    const float* msa_mask = (const float*)d_in[2];
    const float* z_mask   = (const float*)d_in[3];
    const float* ln_m_g   = (const float*)d_in[4];
    const float* ln_m_b   = (const float*)d_in[5];
    const float* W_v      = (const float*)d_in[6];
    const float* W_g      = (const float*)d_in[7];
    const float* ln_z_g   = (const float*)d_in[8];
    const float* ln_z_b   = (const float*)d_in[9];
    const float* W_b      = (const float*)d_in[10];
    const float* W_o      = (const float*)d_in[11];
    float* out = (float*)d_out;

    const int SMEM_VG  = (64 * 260 + 64 * 36) * 4;          // 75776
    const int SMEM_OUT = (256 * 68 + 256 * 66) * 4;         // 137216
    cudaFuncSetAttribute(k_vg<0>, cudaFuncAttributeMaxDynamicSharedMemorySize, SMEM_VG);
    cudaFuncSetAttribute(k_vg<1>, cudaFuncAttributeMaxDynamicSharedMemorySize, SMEM_VG);
    cudaFuncSetAttribute(k_out,   cudaFuncAttributeMaxDynamicSharedMemorySize, SMEM_OUT);

    k_ln_m<<<S_ * I_ / 8, 256>>>(m, ln_m_g, ln_m_b);
    k_vg<0><<<S_ * I_ / 32, 256, SMEM_VG>>>(W_v, msa_mask);
    k_vg<1><<<S_ * I_ / 32, 256, SMEM_VG>>>(W_g, msa_mask);
    k_b<<<I_ * I_ / 8, 256>>>(z, ln_z_g, ln_z_b, W_b, z_mask);
    k_softmax<<<H_ * I_ / 8, 256>>>();
    dim3 eg(NN / 128, I_ / 128, H_);
    k_einsum<<<eg, 256>>>();
    k_out<<<S_ * I_ / 64, 256, SMEM_OUT>>>(W_o, out);
}

// round 2
// speedup vs baseline: 1.7684x; 1.7684x over previous
#include <cuda_runtime.h>
#include <math.h>

#define S_  256
#define I_  512
#define CM  64
#define CZ  128
#define H_  8
#define CH  32
#define HC  256
#define NN  (S_*CH)   // 8192
#define EPS 1e-5f

// ---- scratch ----
__device__ float d_mln[(size_t)S_*I_*CM];
__device__ float d_vbuf[(size_t)H_*I_*S_*CH]; // v in [h][j][s][c]
__device__ float d_gbuf[(size_t)S_*I_*HC];    // sigmoid(g) in [s][i][hc]
__device__ float d_bw[(size_t)H_*I_*I_];      // b/w in [h][i][j]
__device__ float d_obuf[(size_t)H_*I_*NN];    // o in [h][i][s*32+c]

__device__ __forceinline__ float warp_sum(float v) {
#pragma unroll
    for (int o = 16; o; o >>= 1) v += __shfl_xor_sync(0xffffffffu, v, o);
    return v;
}
__device__ __forceinline__ float warp_max(float v) {
#pragma unroll
    for (int o = 16; o; o >>= 1) v = fmaxf(v, __shfl_xor_sync(0xffffffffu, v, o));
    return v;
}
__device__ __forceinline__ unsigned f2tf(float x) {
    unsigned r; asm("cvt.rna.tf32.f32 %0, %1;" : "=r"(r) : "f"(x)); return r;
}
__device__ __forceinline__ float tfs(float x) { return __uint_as_float(f2tf(x)); }

#define MMA_TF32(d0,d1,d2,d3,a0,a1,a2,a3,b0,b1) \
    asm volatile("mma.sync.aligned.m16n8k8.row.col.f32.tf32.tf32.f32 " \
                 "{%0,%1,%2,%3},{%4,%5,%6,%7},{%8,%9},{%0,%1,%2,%3};" \
                 : "+f"(d0),"+f"(d1),"+f"(d2),"+f"(d3) \
                 : "r"(a0),"r"(a1),"r"(a2),"r"(a3),"r"(b0),"r"(b1))

// ---------------- K1: LayerNorm(m) ----------------
__global__ void k_ln_m(const float* __restrict__ m, const float* __restrict__ g,
                       const float* __restrict__ b) {
    int row  = blockIdx.x * 8 + (threadIdx.x >> 5);
    int lane = threadIdx.x & 31;
    const float* x = m + (size_t)row * CM;
    float v0 = x[lane], v1 = x[lane + 32];
    float mu = warp_sum(v0 + v1) * (1.f / 64.f);
    float d0 = v0 - mu, d1 = v1 - mu;
    float var = warp_sum(d0 * d0 + d1 * d1) * (1.f / 64.f);
    float rs = rsqrtf(var + EPS);
    float* y = d_mln + (size_t)row * CM;
    y[lane]      = d0 * rs * g[lane]      + b[lane];
    y[lane + 32] = d1 * rs * g[lane + 32] + b[lane + 32];
}

// ------- K2: fused v+g projection, tf32 MMA.  M=131072, N=512, K=64 -------
// block 128x128, single K pass. cols [0,256)=v, [256,512)=g.
__global__ void __launch_bounds__(256, 2) k_vg_tc(const float* __restrict__ Wv,
                                                  const float* __restrict__ Wg,
                                                  const float* __restrict__ msk) {
    extern __shared__ float sm[];
    float (*As)[68]  = (float(*)[68])sm;               // [128][68]  As[m][k]
    float (*Bs)[132] = (float(*)[132])(sm + 128 * 68); // [64][132]  Bs[k][n]
    int t = threadIdx.x;
    int lane = t & 31, warp = t >> 5;
    int g = lane >> 2, tg = lane & 3;
    int wr = warp >> 2, wc = warp & 3;
    int mBase = blockIdx.y * 128, nBase = blockIdx.x * 128;

    // A tile: 128 rows x 64 k
#pragma unroll
    for (int q = 0; q < 8; q++) {
        int i = q * 256 + t;
        int mm = i >> 4, kf = i & 15;
        float4 v4 = *(const float4*)(d_mln + (size_t)(mBase + mm) * CM + kf * 4);
        float4 c4 = make_float4(tfs(v4.x), tfs(v4.y), tfs(v4.z), tfs(v4.w));
        *(float4*)&As[mm][kf * 4] = c4;
    }
    // B tile: Bs[k][n] from W[n][k]
#pragma unroll
    for (int q = 0; q < 8; q++) {
        int i = q * 256 + t;
        int n = i & 127, kf = i >> 7;
        int col = nBase + n;
        const float* Wp = (col < 256) ? (Wv + (size_t)col * CM)
                                      : (Wg + (size_t)(col - 256) * CM);
        float4 v4 = *(const float4*)(Wp + kf * 4);
        Bs[kf * 4 + 0][n] = tfs(v4.x);
        Bs[kf * 4 + 1][n] = tfs(v4.y);
        Bs[kf * 4 + 2][n] = tfs(v4.z);
        Bs[kf * 4 + 3][n] = tfs(v4.w);
    }
    __syncthreads();

    float acc[4][4][4];
#pragma unroll
    for (int a = 0; a < 4; a++)
#pragma unroll
        for (int b = 0; b < 4; b++)
#pragma unroll
            for (int c = 0; c < 4; c++) acc[a][b][c] = 0.f;

#pragma unroll
    for (int ks = 0; ks < 8; ks++) {
        int kk = ks * 8;
        unsigned Af[4][4], Bf[4][2];
#pragma unroll
        for (int mt = 0; mt < 4; mt++) {
            int m0 = wr * 64 + mt * 16;
            Af[mt][0] = __float_as_uint(As[m0 + g][kk + tg]);
            Af[mt][1] = __float_as_uint(As[m0 + g + 8][kk + tg]);
            Af[mt][2] = __float_as_uint(As[m0 + g][kk + tg + 4]);
            Af[mt][3] = __float_as_uint(As[m0 + g + 8][kk + tg + 4]);
        }
#pragma unroll
        for (int nt = 0; nt < 4; nt++) {
            int n0 = wc * 32 + nt * 8;
            Bf[nt][0] = __float_as_uint(Bs[kk + tg][n0 + g]);
            Bf[nt][1] = __float_as_uint(Bs[kk + tg + 4][n0 + g]);
        }
#pragma unroll
        for (int mt = 0; mt < 4; mt++)
#pragma unroll
            for (int nt = 0; nt < 4; nt++)
                MMA_TF32(acc[mt][nt][0], acc[mt][nt][1], acc[mt][nt][2], acc[mt][nt][3],
                         Af[mt][0], Af[mt][1], Af[mt][2], Af[mt][3],
                         Bf[nt][0], Bf[nt][1]);
    }

    // epilogue
#pragma unroll
    for (int mt = 0; mt < 4; mt++) {
        int R0 = mBase + wr * 64 + mt * 16 + g;
        int R1 = R0 + 8;
        float mk0 = msk[R0], mk1 = msk[R1];
#pragma unroll
        for (int nt = 0; nt < 4; nt++) {
            int Cc = nBase + wc * 32 + nt * 8 + 2 * tg;
            if (Cc < 256) {
                int h = Cc >> 5, c = Cc & 31;
                {
                    int s = R0 >> 9, j = R0 & 511;
                    float2 o = make_float2(acc[mt][nt][0] * mk0, acc[mt][nt][1] * mk0);
                    *(float2*)(d_vbuf + (((size_t)h * I_ + j) * S_ + s) * CH + c) = o;
                }
                {
                    int s = R1 >> 9, j = R1 & 511;
                    float2 o = make_float2(acc[mt][nt][2] * mk1, acc[mt][nt][3] * mk1);
                    *(float2*)(d_vbuf + (((size_t)h * I_ + j) * S_ + s) * CH + c) = o;
                }
            } else {
                int cg = Cc - 256;
                float2 o0 = make_float2(1.f / (1.f + __expf(-acc[mt][nt][0])),
                                        1.f / (1.f + __expf(-acc[mt][nt][1])));
                float2 o1 = make_float2(1.f / (1.f + __expf(-acc[mt][nt][2])),
                                        1.f / (1.f + __expf(-acc[mt][nt][3])));
                *(float2*)(d_gbuf + (size_t)R0 * HC + cg) = o0;
                *(float2*)(d_gbuf + (size_t)R1 * HC + cg) = o1;
            }
        }
    }
}

// ---- K3: b[h][i][j] = LN(z[i][j]) . W_b[h] + INF*(zmask-1) ----
__global__ void k_b(const float* __restrict__ z, const float* __restrict__ zg,
                    const float* __restrict__ zb, const float* __restrict__ Wb,
                    const float* __restrict__ zmask) {
    __shared__ __align__(16) float Wbs[H_ * CZ];
    __shared__ float zgs[CZ], zbs[CZ];
    __shared__ float outs[8][9];   // [jj][h]
    int t = threadIdx.x;
    for (int idx = t; idx < H_ * CZ; idx += 256) Wbs[idx] = Wb[idx];
    if (t < CZ) { zgs[t] = zg[t]; zbs[t] = zb[t]; }
    __syncthreads();

    int w = blockIdx.x * 8 + (t >> 5);
    int lane = t & 31;
    const float4 zv = *(const float4*)(z + (size_t)w * CZ + lane * 4);
    float mu = warp_sum(zv.x + zv.y + zv.z + zv.w) * (1.f / 128.f);
    float e0 = zv.x - mu, e1 = zv.y - mu, e2 = zv.z - mu, e3 = zv.w - mu;
    float var = warp_sum(e0 * e0 + e1 * e1 + e2 * e2 + e3 * e3) * (1.f / 128.f);
    float rs = rsqrtf(var + EPS);
    int k0 = lane * 4;
    float l0 = e0 * rs * zgs[k0]     + zbs[k0];
    float l1 = e1 * rs * zgs[k0 + 1] + zbs[k0 + 1];
    float l2 = e2 * rs * zgs[k0 + 2] + zbs[k0 + 2];
    float l3 = e3 * rs * zgs[k0 + 3] + zbs[k0 + 3];

    float p[8];
#pragma unroll
    for (int h = 0; h < 8; h++) {
        float4 w4 = *(const float4*)(Wbs + h * CZ + k0);
        p[h] = l0 * w4.x + l1 * w4.y + l2 * w4.z + l3 * w4.w;
    }
    // multi-value butterfly: 8 vals over 32 lanes in 9 shuffles
    bool hi16 = (lane & 16), hi8 = (lane & 8), hi4 = (lane & 4);
    float q[4];
#pragma unroll
    for (int h = 0; h < 4; h++) {
        float send = hi16 ? p[h] : p[h + 4];
        float recv = __shfl_xor_sync(0xffffffffu, send, 16);
        q[h] = (hi16 ? p[h + 4] : p[h]) + recv;
    }
    float r_[2];
#pragma unroll
    for (int h = 0; h < 2; h++) {
        float send = hi8 ? q[h] : q[h + 2];
        float recv = __shfl_xor_sync(0xffffffffu, send, 8);
        r_[h] = (hi8 ? q[h + 2] : q[h]) + recv;
    }
    {
        float send = hi4 ? r_[0] : r_[1];
        float recv = __shfl_xor_sync(0xffffffffu, send, 4);
        float val = (hi4 ? r_[1] : r_[0]) + recv;
        val += __shfl_xor_sync(0xffffffffu, val, 2);
        val += __shfl_xor_sync(0xffffffffu, val, 1);
        int hmine = (((lane >> 4) & 1) << 2) | (((lane >> 3) & 1) << 1) | ((lane >> 2) & 1);
        if ((lane & 3) == 0) outs[t >> 5][hmine] = val;
    }
    __syncthreads();
    if (t < 64) {
        int hh = t >> 3, jj = t & 7;
        int base = blockIdx.x * 8;
        int i = base >> 9, j0 = base & 511;
        float mval = zmask[base + jj];
        d_bw[((size_t)hh * I_ + i) * I_ + j0 + jj] = outs[jj][hh] + 1e8f * (mval - 1.f);
    }
}

// ---------------- K4: softmax over j ----------------
__global__ void k_softmax() {
    int row  = blockIdx.x * 8 + (threadIdx.x >> 5);
    int lane = threadIdx.x & 31;
    float* p = d_bw + (size_t)row * I_;
    float4 x[4];
#pragma unroll
    for (int q = 0; q < 4; q++) x[q] = *(float4*)(p + q * 128 + lane * 4);
    float mx = -3.4e38f;
#pragma unroll
    for (int q = 0; q < 4; q++)
        mx = fmaxf(mx, fmaxf(fmaxf(x[q].x, x[q].y), fmaxf(x[q].z, x[q].w)));
    mx = warp_max(mx);
    float sum = 0.f;
#pragma unroll
    for (int q = 0; q < 4; q++) {
        x[q].x = __expf(x[q].x - mx); x[q].y = __expf(x[q].y - mx);
        x[q].z = __expf(x[q].z - mx); x[q].w = __expf(x[q].w - mx);
        sum += x[q].x + x[q].y + x[q].z + x[q].w;
    }
    sum = warp_sum(sum);
    float inv = 1.f / sum;
#pragma unroll
    for (int q = 0; q < 4; q++) {
        x[q].x *= inv; x[q].y *= inv; x[q].z *= inv; x[q].w *= inv;
        *(float4*)(p + q * 128 + lane * 4) = x[q];
    }
}

// ---- K5: einsum via tf32 MMA. Per head: O = W[512x512] @ V[512x8192]. ----
// block 128x128, BK=16, double-buffered smem, 8 warps of 64x32 tiles.
__global__ void __launch_bounds__(256, 2) k_einsum_tc() {
    __shared__ float As[2][128][20];   // As[buf][m][k]
    __shared__ float Bs[2][16][132];   // Bs[buf][k][n]
    int h = blockIdx.z;
    const float* A = d_bw   + (size_t)h * I_ * I_;
    const float* B = d_vbuf + (size_t)h * I_ * NN;
    float*       C = d_obuf + (size_t)h * I_ * NN;
    int mBase = blockIdx.y * 128, nBase = blockIdx.x * 128;
    int t = threadIdx.x;
    int lane = t & 31, warp = t >> 5;
    int g = lane >> 2, tg = lane & 3;
    int wr = warp >> 2, wc = warp & 3;

    int amr = t >> 2, akq = t & 3;       // A: rows amr, amr+64 ; float4 idx akq
    int bkr = t >> 5, bn4 = t & 31;      // B: rows bkr, bkr+8 ; float4 idx bn4

    const float* Ap0 = A + (size_t)(mBase + amr) * I_ + akq * 4;
    const float* Ap1 = Ap0 + (size_t)64 * I_;
    const float* Bp0 = B + (size_t)bkr * NN + nBase + bn4 * 4;
    const float* Bp1 = Bp0 + (size_t)8 * NN;

    // prologue: tile 0
    {
        float4 a0 = *(const float4*)Ap0;
        float4 a1 = *(const float4*)Ap1;
        float4 b0 = *(const float4*)Bp0;
        float4 b1 = *(const float4*)Bp1;
        *(float4*)&As[0][amr][akq * 4]      = make_float4(tfs(a0.x), tfs(a0.y), tfs(a0.z), tfs(a0.w));
        *(float4*)&As[0][amr + 64][akq * 4] = make_float4(tfs(a1.x), tfs(a1.y), tfs(a1.z), tfs(a1.w));
        *(float4*)&Bs[0][bkr][bn4 * 4]      = make_float4(tfs(b0.x), tfs(b0.y), tfs(b0.z), tfs(b0.w));
        *(float4*)&Bs[0][bkr + 8][bn4 * 4]  = make_float4(tfs(b1.x), tfs(b1.y), tfs(b1.z), tfs(b1.w));
    }
    __syncthreads();

    float acc[4][4][4];
#pragma unroll
    for (int a = 0; a < 4; a++)
#pragma unroll
        for (int b = 0; b < 4; b++)
#pragma unroll
            for (int c = 0; c < 4; c++) acc[a][b][c] = 0.f;

    float4 pa0, pa1, pb0, pb1;
    for (int it = 0; it < 32; ++it) {
        int cur = it & 1;
        if (it < 31) {
            int k0 = (it + 1) * 16;
            pa0 = *(const float4*)(Ap0 + k0);
            pa1 = *(const float4*)(Ap1 + k0);
            pb0 = *(const float4*)(Bp0 + (size_t)k0 * NN);
            pb1 = *(const float4*)(Bp1 + (size_t)k0 * NN);
        }
#pragma unroll
        for (int ks = 0; ks < 2; ks++) {
            int kk = ks * 8;
            unsigned Af[4][4], Bf[4][2];
#pragma unroll
            for (int mt = 0; mt < 4; mt++) {
                int m0 = wr * 64 + mt * 16;
                Af[mt][0] = __float_as_uint(As[cur][m0 + g][kk + tg]);
                Af[mt][1] = __float_as_uint(As[cur][m0 + g + 8][kk + tg]);
                Af[mt][2] = __float_as_uint(As[cur][m0 + g][kk + tg + 4]);
                Af[mt][3] = __float_as_uint(As[cur][m0 + g + 8][kk + tg + 4]);
            }
#pragma unroll
            for (int nt = 0; nt < 4; nt++) {
                int n0 = wc * 32 + nt * 8;
                Bf[nt][0] = __float_as_uint(Bs[cur][kk + tg][n0 + g]);
                Bf[nt][1] = __float_as_uint(Bs[cur][kk + tg + 4][n0 + g]);
            }
#pragma unroll
            for (int mt = 0; mt < 4; mt++)
#pragma unroll
                for (int nt = 0; nt < 4; nt++)
                    MMA_TF32(acc[mt][nt][0], acc[mt][nt][1], acc[mt][nt][2], acc[mt][nt][3],
                             Af[mt][0], Af[mt][1], Af[mt][2], Af[mt][3],
                             Bf[nt][0], Bf[nt][1]);
        }
        if (it < 31) {
            int nb = cur ^ 1;
            *(float4*)&As[nb][amr][akq * 4]      = make_float4(tfs(pa0.x), tfs(pa0.y), tfs(pa0.z), tfs(pa0.w));
            *(float4*)&As[nb][amr + 64][akq * 4] = make_float4(tfs(pa1.x), tfs(pa1.y), tfs(pa1.z), tfs(pa1.w));
            *(float4*)&Bs[nb][bkr][bn4 * 4]      = make_float4(tfs(pb0.x), tfs(pb0.y), tfs(pb0.z), tfs(pb0.w));
            *(float4*)&Bs[nb][bkr + 8][bn4 * 4]  = make_float4(tfs(pb1.x), tfs(pb1.y), tfs(pb1.z), tfs(pb1.w));
            __syncthreads();
        }
    }

#pragma unroll
    for (int mt = 0; mt < 4; mt++) {
        int R0 = mBase + wr * 64 + mt * 16 + g;
#pragma unroll
        for (int nt = 0; nt < 4; nt++) {
            int col = nBase + wc * 32 + nt * 8 + 2 * tg;
            *(float2*)(C + (size_t)R0 * NN + col)       = make_float2(acc[mt][nt][0], acc[mt][nt][1]);
            *(float2*)(C + (size_t)(R0 + 8) * NN + col) = make_float2(acc[mt][nt][2], acc[mt][nt][3]);
        }
    }
}

// ---- K6: out = (g * gather(o)) @ W_o^T ----
__global__ void __launch_bounds__(256) k_out(const float* __restrict__ Wo,
                                             float* __restrict__ out) {
    extern __shared__ float sm[];
    float* WoT = sm;              // [256][68]
    float* aT  = sm + 256 * 68;   // [256][66]
    int t = threadIdx.x;
#pragma unroll 4
    for (int q = 0; q < 64; q++) {
        int idx = q * 256 + t;
        int cm = idx >> 8, k = idx & 255;
        WoT[k * 68 + cm] = Wo[idx];
    }
    int rowBase = blockIdx.x * 64;
#pragma unroll 4
    for (int q = 0; q < 64; q++) {
        int idx = q * 256 + t;
        int r = idx >> 8, kk = idx & 255;
        int gr = rowBase + r;
        int s = gr >> 9, i = gr & 511;
        int h = kk >> 5, c = kk & 31;
        float gv = d_gbuf[(size_t)gr * HC + kk];
        float ov = d_obuf[((size_t)h * I_ + i) * NN + s * CH + c];
        aT[kk * 66 + r] = gv * ov;
    }
    __syncthreads();
    int tx = t & 15, ty = t >> 4;
    float acc[4][4];
#pragma unroll
    for (int r = 0; r < 4; r++)
#pragma unroll
        for (int c = 0; c < 4; c++) acc[r][c] = 0.f;

#pragma unroll 4
    for (int k = 0; k < 256; k++) {
        float4 w4 = *(const float4*)(WoT + k * 68 + tx * 4);
#pragma unroll
        for (int r = 0; r < 4; r++) {
            float a = aT[k * 66 + ty * 4 + r];
            acc[r][0] += a * w4.x;
            acc[r][1] += a * w4.y;
            acc[r][2] += a * w4.z;
            acc[r][3] += a * w4.w;
        }
    }
#pragma unroll
    for (int r = 0; r < 4; r++) {
        *(float4*)(out + (size_t)(rowBase + ty * 4 + r) * CM + tx * 4) =
            make_float4(acc[r][0], acc[r][1], acc[r][2], acc[r][3]);
    }
}

extern "C" void kernel_launch(void* const* d_in, const int* in_sizes, int n_in,
                              void* d_out, int out_size) {
    const float* m        = (const float*)d_in[0];
    const float* z        = (const float*)d_in[1];
    const float* msa_mask = (const float*)d_in[2];
    const float* z_mask   = (const float*)d_in[3];
    const float* ln_m_g   = (const float*)d_in[4];
    const float* ln_m_b   = (const float*)d_in[5];
    const float* W_v      = (const float*)d_in[6];
    const float* W_g      = (const float*)d_in[7];
    const float* ln_z_g   = (const float*)d_in[8];
    const float* ln_z_b   = (const float*)d_in[9];
    const float* W_b      = (const float*)d_in[10];
    const float* W_o      = (const float*)d_in[11];
    float* out = (float*)d_out;

    const int SMEM_VG  = (128 * 68 + 64 * 132) * 4;   // 68608
    const int SMEM_OUT = (256 * 68 + 256 * 66) * 4;   // 137216
    cudaFuncSetAttribute(k_vg_tc, cudaFuncAttributeMaxDynamicSharedMemorySize, SMEM_VG);
    cudaFuncSetAttribute(k_out,   cudaFuncAttributeMaxDynamicSharedMemorySize, SMEM_OUT);

    k_ln_m<<<S_ * I_ / 8, 256>>>(m, ln_m_g, ln_m_b);
    k_vg_tc<<<dim3(4, 1024), 256, SMEM_VG>>>(W_v, W_g, msa_mask);
    k_b<<<I_ * I_ / 8, 256>>>(z, ln_z_g, ln_z_b, W_b, z_mask);
    k_softmax<<<H_ * I_ / 8, 256>>>();
    k_einsum_tc<<<dim3(NN / 128, I_ / 128, H_), 256>>>();
    k_out<<<S_ * I_ / 64, 256, SMEM_OUT>>>(W_o, out);
}

// round 4
// speedup vs baseline: 1.8953x; 1.0718x over previous
#include <cuda_runtime.h>
#include <cuda_fp16.h>
#include <math.h>
#include <cstdint>

#define S_  256
#define I_  512
#define CM  64
#define CZ  128
#define H_  8
#define CH  32
#define HC  256
#define NN  (S_*CH)   // 8192
#define EPS 1e-5f

// ---- scratch ----
__device__ float  d_mln[(size_t)S_*I_*CM];
__device__ __half d_vh[(size_t)H_*NN*I_];     // v fp16 in [h][n][j], n = s*32+c (64 MB)
__device__ float  d_gbuf[(size_t)S_*I_*HC];   // sigmoid(g) fp32 [s*i][hc]
__device__ float  d_bw[(size_t)H_*I_*I_];     // b fp32 [h][i][j]
__device__ __half d_wh[(size_t)H_*I_*I_];     // softmax(w) fp16 [h][i][j] (4 MB)
__device__ float  d_obuf[(size_t)H_*I_*NN];   // o fp32 [h][i][n]

__device__ __forceinline__ float warp_sum(float v) {
#pragma unroll
    for (int o = 16; o; o >>= 1) v += __shfl_xor_sync(0xffffffffu, v, o);
    return v;
}
__device__ __forceinline__ float warp_max(float v) {
#pragma unroll
    for (int o = 16; o; o >>= 1) v = fmaxf(v, __shfl_xor_sync(0xffffffffu, v, o));
    return v;
}
__device__ __forceinline__ unsigned f2tf(float x) {
    unsigned r; asm("cvt.rna.tf32.f32 %0, %1;" : "=r"(r) : "f"(x)); return r;
}
__device__ __forceinline__ float tfs(float x) { return __uint_as_float(f2tf(x)); }

#define MMA_TF32(d0,d1,d2,d3,a0,a1,a2,a3,b0,b1) \
    asm volatile("mma.sync.aligned.m16n8k8.row.col.f32.tf32.tf32.f32 " \
                 "{%0,%1,%2,%3},{%4,%5,%6,%7},{%8,%9},{%0,%1,%2,%3};" \
                 : "+f"(d0),"+f"(d1),"+f"(d2),"+f"(d3) \
                 : "r"(a0),"r"(a1),"r"(a2),"r"(a3),"r"(b0),"r"(b1))

#define MMA_F16(d0,d1,d2,d3,a0,a1,a2,a3,b0,b1) \
    asm volatile("mma.sync.aligned.m16n8k16.row.col.f32.f16.f16.f32 " \
                 "{%0,%1,%2,%3},{%4,%5,%6,%7},{%8,%9},{%0,%1,%2,%3};" \
                 : "+f"(d0),"+f"(d1),"+f"(d2),"+f"(d3) \
                 : "r"(a0),"r"(a1),"r"(a2),"r"(a3),"r"(b0),"r"(b1))

// ---------------- K1: LayerNorm(m) ----------------
__global__ void k_ln_m(const float* __restrict__ m, const float* __restrict__ g,
                       const float* __restrict__ b) {
    int row  = blockIdx.x * 8 + (threadIdx.x >> 5);
    int lane = threadIdx.x & 31;
    const float* x = m + (size_t)row * CM;
    float v0 = x[lane], v1 = x[lane + 32];
    float mu = warp_sum(v0 + v1) * (1.f / 64.f);
    float d0 = v0 - mu, d1 = v1 - mu;
    float var = warp_sum(d0 * d0 + d1 * d1) * (1.f / 64.f);
    float rs = rsqrtf(var + EPS);
    float* y = d_mln + (size_t)row * CM;
    y[lane]      = d0 * rs * g[lane]      + b[lane];
    y[lane + 32] = d1 * rs * g[lane + 32] + b[lane + 32];
}

// ------- K2: fused v+g projection, tf32 MMA; v -> fp16 [h][n][j] -------
__global__ void __launch_bounds__(256, 2) k_vg_tc(const float* __restrict__ Wv,
                                                  const float* __restrict__ Wg,
                                                  const float* __restrict__ msk) {
    extern __shared__ float sm[];
    float (*As)[68]  = (float(*)[68])sm;
    float (*Bs)[132] = (float(*)[132])(sm + 128 * 68);
    int t = threadIdx.x;
    int lane = t & 31, warp = t >> 5;
    int g = lane >> 2, tg = lane & 3;
    int wr = warp >> 2, wc = warp & 3;
    int mBase = blockIdx.y * 128, nBase = blockIdx.x * 128;

#pragma unroll
    for (int q = 0; q < 8; q++) {
        int i = q * 256 + t;
        int mm = i >> 4, kf = i & 15;
        float4 v4 = *(const float4*)(d_mln + (size_t)(mBase + mm) * CM + kf * 4);
        *(float4*)&As[mm][kf * 4] = make_float4(tfs(v4.x), tfs(v4.y), tfs(v4.z), tfs(v4.w));
    }
#pragma unroll
    for (int q = 0; q < 8; q++) {
        int i = q * 256 + t;
        int n = i & 127, kf = i >> 7;
        int col = nBase + n;
        const float* Wp = (col < 256) ? (Wv + (size_t)col * CM)
                                      : (Wg + (size_t)(col - 256) * CM);
        float4 v4 = *(const float4*)(Wp + kf * 4);
        Bs[kf * 4 + 0][n] = tfs(v4.x);
        Bs[kf * 4 + 1][n] = tfs(v4.y);
        Bs[kf * 4 + 2][n] = tfs(v4.z);
        Bs[kf * 4 + 3][n] = tfs(v4.w);
    }
    __syncthreads();

    float acc[4][4][4];
#pragma unroll
    for (int a = 0; a < 4; a++)
#pragma unroll
        for (int b = 0; b < 4; b++)
#pragma unroll
            for (int c = 0; c < 4; c++) acc[a][b][c] = 0.f;

#pragma unroll
    for (int ks = 0; ks < 8; ks++) {
        int kk = ks * 8;
        unsigned Af[4][4], Bf[4][2];
#pragma unroll
        for (int mt = 0; mt < 4; mt++) {
            int m0 = wr * 64 + mt * 16;
            Af[mt][0] = __float_as_uint(As[m0 + g][kk + tg]);
            Af[mt][1] = __float_as_uint(As[m0 + g + 8][kk + tg]);
            Af[mt][2] = __float_as_uint(As[m0 + g][kk + tg + 4]);
            Af[mt][3] = __float_as_uint(As[m0 + g + 8][kk + tg + 4]);
        }
#pragma unroll
        for (int nt = 0; nt < 4; nt++) {
            int n0 = wc * 32 + nt * 8;
            Bf[nt][0] = __float_as_uint(Bs[kk + tg][n0 + g]);
            Bf[nt][1] = __float_as_uint(Bs[kk + tg + 4][n0 + g]);
        }
#pragma unroll
        for (int mt = 0; mt < 4; mt++)
#pragma unroll
            for (int nt = 0; nt < 4; nt++)
                MMA_TF32(acc[mt][nt][0], acc[mt][nt][1], acc[mt][nt][2], acc[mt][nt][3],
                         Af[mt][0], Af[mt][1], Af[mt][2], Af[mt][3],
                         Bf[nt][0], Bf[nt][1]);
    }

#pragma unroll
    for (int mt = 0; mt < 4; mt++) {
        int R0 = mBase + wr * 64 + mt * 16 + g;
        int R1 = R0 + 8;
        float mk0 = msk[R0], mk1 = msk[R1];
#pragma unroll
        for (int nt = 0; nt < 4; nt++) {
            int Cc = nBase + wc * 32 + nt * 8 + 2 * tg;
            if (Cc < 256) {
                int hh = Cc >> 5, c = Cc & 31;
                int s = R0 >> 9, j = R0 & 511;   // R1 = R0+8 -> same s, j+8
                __half* vp = d_vh + ((size_t)hh * NN + (size_t)s * CH + c) * I_ + j;
                vp[0]       = __float2half(acc[mt][nt][0] * mk0);
                vp[I_]      = __float2half(acc[mt][nt][1] * mk0);
                vp[8]       = __float2half(acc[mt][nt][2] * mk1);
                vp[I_ + 8]  = __float2half(acc[mt][nt][3] * mk1);
            } else {
                int cg = Cc - 256;
                float2 o0 = make_float2(1.f / (1.f + __expf(-acc[mt][nt][0])),
                                        1.f / (1.f + __expf(-acc[mt][nt][1])));
                float2 o1 = make_float2(1.f / (1.f + __expf(-acc[mt][nt][2])),
                                        1.f / (1.f + __expf(-acc[mt][nt][3])));
                *(float2*)(d_gbuf + (size_t)R0 * HC + cg) = o0;
                *(float2*)(d_gbuf + (size_t)R1 * HC + cg) = o1;
            }
        }
    }
}

// ---- K3: b[h][i][j] = LN(z[i][j]) . W_b[h] + INF*(zmask-1) ----
__global__ void k_b(const float* __restrict__ z, const float* __restrict__ zg,
                    const float* __restrict__ zb, const float* __restrict__ Wb,
                    const float* __restrict__ zmask) {
    __shared__ __align__(16) float Wbs[H_ * CZ];
    __shared__ float zgs[CZ], zbs[CZ];
    __shared__ float outs[8][9];
    int t = threadIdx.x;
    for (int idx = t; idx < H_ * CZ; idx += 256) Wbs[idx] = Wb[idx];
    if (t < CZ) { zgs[t] = zg[t]; zbs[t] = zb[t]; }
    __syncthreads();

    int w = blockIdx.x * 8 + (t >> 5);
    int lane = t & 31;
    const float4 zv = *(const float4*)(z + (size_t)w * CZ + lane * 4);
    float mu = warp_sum(zv.x + zv.y + zv.z + zv.w) * (1.f / 128.f);
    float e0 = zv.x - mu, e1 = zv.y - mu, e2 = zv.z - mu, e3 = zv.w - mu;
    float var = warp_sum(e0 * e0 + e1 * e1 + e2 * e2 + e3 * e3) * (1.f / 128.f);
    float rs = rsqrtf(var + EPS);
    int k0 = lane * 4;
    float l0 = e0 * rs * zgs[k0]     + zbs[k0];
    float l1 = e1 * rs * zgs[k0 + 1] + zbs[k0 + 1];
    float l2 = e2 * rs * zgs[k0 + 2] + zbs[k0 + 2];
    float l3 = e3 * rs * zgs[k0 + 3] + zbs[k0 + 3];

    float p[8];
#pragma unroll
    for (int h = 0; h < 8; h++) {
        float4 w4 = *(const float4*)(Wbs + h * CZ + k0);
        p[h] = l0 * w4.x + l1 * w4.y + l2 * w4.z + l3 * w4.w;
    }
    bool hi16 = (lane & 16), hi8 = (lane & 8), hi4 = (lane & 4);
    float q[4];
#pragma unroll
    for (int h = 0; h < 4; h++) {
        float send = hi16 ? p[h] : p[h + 4];
        float recv = __shfl_xor_sync(0xffffffffu, send, 16);
        q[h] = (hi16 ? p[h + 4] : p[h]) + recv;
    }
    float r_[2];
#pragma unroll
    for (int h = 0; h < 2; h++) {
        float send = hi8 ? q[h] : q[h + 2];
        float recv = __shfl_xor_sync(0xffffffffu, send, 8);
        r_[h] = (hi8 ? q[h + 2] : q[h]) + recv;
    }
    {
        float send = hi4 ? r_[0] : r_[1];
        float recv = __shfl_xor_sync(0xffffffffu, send, 4);
        float val = (hi4 ? r_[1] : r_[0]) + recv;
        val += __shfl_xor_sync(0xffffffffu, val, 2);
        val += __shfl_xor_sync(0xffffffffu, val, 1);
        int hmine = (((lane >> 4) & 1) << 2) | (((lane >> 3) & 1) << 1) | ((lane >> 2) & 1);
        if ((lane & 3) == 0) outs[t >> 5][hmine] = val;
    }
    __syncthreads();
    if (t < 64) {
        int hh = t >> 3, jj = t & 7;
        int base = blockIdx.x * 8;
        int i = base >> 9, j0 = base & 511;
        float mval = zmask[base + jj];
        d_bw[((size_t)hh * I_ + i) * I_ + j0 + jj] = outs[jj][hh] + 1e8f * (mval - 1.f);
    }
}

// ---------------- K4: softmax over j; output fp16 to d_wh ----------------
__global__ void k_softmax() {
    int row  = blockIdx.x * 8 + (threadIdx.x >> 5);
    int lane = threadIdx.x & 31;
    const float* p = d_bw + (size_t)row * I_;
    float4 x[4];
#pragma unroll
    for (int q = 0; q < 4; q++) x[q] = *(const float4*)(p + q * 128 + lane * 4);
    float mx = -3.4e38f;
#pragma unroll
    for (int q = 0; q < 4; q++)
        mx = fmaxf(mx, fmaxf(fmaxf(x[q].x, x[q].y), fmaxf(x[q].z, x[q].w)));
    mx = warp_max(mx);
    float sum = 0.f;
#pragma unroll
    for (int q = 0; q < 4; q++) {
        x[q].x = __expf(x[q].x - mx); x[q].y = __expf(x[q].y - mx);
        x[q].z = __expf(x[q].z - mx); x[q].w = __expf(x[q].w - mx);
        sum += x[q].x + x[q].y + x[q].z + x[q].w;
    }
    sum = warp_sum(sum);
    float inv = 1.f / sum;
    __half* wp = d_wh + (size_t)row * I_;
#pragma unroll
    for (int q = 0; q < 4; q++) {
        __half2 h01 = __floats2half2_rn(x[q].x * inv, x[q].y * inv);
        __half2 h23 = __floats2half2_rn(x[q].z * inv, x[q].w * inv);
        *(uint2*)(wp + q * 128 + lane * 4) =
            make_uint2(*(unsigned*)&h01, *(unsigned*)&h23);
    }
}

// ---- K5: einsum via fp16 m16n8k16. Per head: O[i][n] = W[i][j] @ V^T[n][j]. ----
// Block: 128 i x 256 n, BK=32, double-buffered smem (pad 40 halves), reg prefetch.
__global__ void __launch_bounds__(256) k_einsum_h() {
    extern __shared__ __half smh[];
    const int BUF = 15360;   // (128+256)*40 halves per buffer
    int t = threadIdx.x, lane = t & 31, wid = t >> 5;
    int g = lane >> 2, tg = lane & 3;
    int wr = wid & 1, wc = wid >> 1;
    int h = blockIdx.z;
    int mBase = blockIdx.y * 128, nBase = blockIdx.x * 256;
    const __half* Ag = d_wh + ((size_t)h * I_ + mBase) * I_;
    const __half* Bg = d_vh + ((size_t)h * NN + nBase) * I_;
    float*        C  = d_obuf + ((size_t)h * I_ + mBase) * NN + nBase;

    int arow = t & 127, ac4 = t >> 7;   // A rows 0..127, c4 base 0/1
    int brow = t;                        // B rows 0..255

    // prologue: stage kc=0
    {
        const __half* Ap = Ag + (size_t)arow * I_;
        *(uint4*)&smh[arow * 40 + ac4 * 8]       = *(const uint4*)(Ap + ac4 * 8);
        *(uint4*)&smh[arow * 40 + (ac4 + 2) * 8] = *(const uint4*)(Ap + (ac4 + 2) * 8);
        const __half* Bp = Bg + (size_t)brow * I_;
#pragma unroll
        for (int q = 0; q < 4; q++)
            *(uint4*)&smh[5120 + brow * 40 + q * 8] = *(const uint4*)(Bp + q * 8);
    }
    __syncthreads();

    float acc[4][8][4];
#pragma unroll
    for (int a = 0; a < 4; a++)
#pragma unroll
        for (int b = 0; b < 8; b++)
#pragma unroll
            for (int c = 0; c < 4; c++) acc[a][b][c] = 0.f;

    uint4 pa0, pa1, pb[4];
    for (int kc = 0; kc < 16; kc++) {
        int cur = kc & 1;
        if (kc < 15) {
            const __half* Ap = Ag + (size_t)arow * I_ + (kc + 1) * 32;
            pa0 = *(const uint4*)(Ap + ac4 * 8);
            pa1 = *(const uint4*)(Ap + (ac4 + 2) * 8);
            const __half* Bp = Bg + (size_t)brow * I_ + (kc + 1) * 32;
#pragma unroll
            for (int q = 0; q < 4; q++) pb[q] = *(const uint4*)(Bp + q * 8);
        }
        const __half* As = smh + cur * BUF;
        const __half* Bs = smh + cur * BUF + 5120;
#pragma unroll
        for (int ks = 0; ks < 2; ks++) {
            int k0 = ks * 16;
            uint32_t Af[4][4], Bf[8][2];
#pragma unroll
            for (int mt = 0; mt < 4; mt++) {
                int m0 = wr * 64 + mt * 16 + g;
                Af[mt][0] = *(const uint32_t*)&As[(m0)     * 40 + k0 + 2 * tg];
                Af[mt][1] = *(const uint32_t*)&As[(m0 + 8) * 40 + k0 + 2 * tg];
                Af[mt][2] = *(const uint32_t*)&As[(m0)     * 40 + k0 + 2 * tg + 8];
                Af[mt][3] = *(const uint32_t*)&As[(m0 + 8) * 40 + k0 + 2 * tg + 8];
            }
#pragma unroll
            for (int nt = 0; nt < 8; nt++) {
                int n0 = wc * 64 + nt * 8 + g;
                Bf[nt][0] = *(const uint32_t*)&Bs[n0 * 40 + k0 + 2 * tg];
                Bf[nt][1] = *(const uint32_t*)&Bs[n0 * 40 + k0 + 2 * tg + 8];
            }
#pragma unroll
            for (int mt = 0; mt < 4; mt++)
#pragma unroll
                for (int nt = 0; nt < 8; nt++)
                    MMA_F16(acc[mt][nt][0], acc[mt][nt][1], acc[mt][nt][2], acc[mt][nt][3],
                            Af[mt][0], Af[mt][1], Af[mt][2], Af[mt][3],
                            Bf[nt][0], Bf[nt][1]);
        }
        if (kc < 15) {
            __half* Ad = smh + (cur ^ 1) * BUF;
            *(uint4*)&Ad[arow * 40 + ac4 * 8]       = pa0;
            *(uint4*)&Ad[arow * 40 + (ac4 + 2) * 8] = pa1;
            __half* Bd = Ad + 5120;
#pragma unroll
            for (int q = 0; q < 4; q++) *(uint4*)&Bd[brow * 40 + q * 8] = pb[q];
            __syncthreads();
        }
    }

#pragma unroll
    for (int mt = 0; mt < 4; mt++) {
        int r = wr * 64 + mt * 16 + g;
#pragma unroll
        for (int nt = 0; nt < 8; nt++) {
            int col = wc * 64 + nt * 8 + 2 * tg;
            *(float2*)(C + (size_t)r * NN + col)       = make_float2(acc[mt][nt][0], acc[mt][nt][1]);
            *(float2*)(C + (size_t)(r + 8) * NN + col) = make_float2(acc[mt][nt][2], acc[mt][nt][3]);
        }
    }
}

// ---- K6: out = (g * gather(o)) @ W_o^T ----
__global__ void __launch_bounds__(256) k_out(const float* __restrict__ Wo,
                                             float* __restrict__ out) {
    extern __shared__ float sm[];
    float* WoT = sm;              // [256][68]
    float* aT  = sm + 256 * 68;   // [256][66]
    int t = threadIdx.x;
#pragma unroll 4
    for (int q = 0; q < 64; q++) {
        int idx = q * 256 + t;
        int cm = idx >> 8, k = idx & 255;
        WoT[k * 68 + cm] = Wo[idx];
    }
    int rowBase = blockIdx.x * 64;
#pragma unroll 4
    for (int q = 0; q < 64; q++) {
        int idx = q * 256 + t;
        int r = idx >> 8, kk = idx & 255;
        int gr = rowBase + r;
        int s = gr >> 9, i = gr & 511;
        int h = kk >> 5, c = kk & 31;
        float gv = d_gbuf[(size_t)gr * HC + kk];
        float ov = d_obuf[((size_t)h * I_ + i) * NN + s * CH + c];
        aT[kk * 66 + r] = gv * ov;
    }
    __syncthreads();
    int tx = t & 15, ty = t >> 4;
    float acc[4][4];
#pragma unroll
    for (int r = 0; r < 4; r++)
#pragma unroll
        for (int c = 0; c < 4; c++) acc[r][c] = 0.f;

#pragma unroll 4
    for (int k = 0; k < 256; k++) {
        float4 w4 = *(const float4*)(WoT + k * 68 + tx * 4);
#pragma unroll
        for (int r = 0; r < 4; r++) {
            float a = aT[k * 66 + ty * 4 + r];
            acc[r][0] += a * w4.x;
            acc[r][1] += a * w4.y;
            acc[r][2] += a * w4.z;
            acc[r][3] += a * w4.w;
        }
    }
#pragma unroll
    for (int r = 0; r < 4; r++) {
        *(float4*)(out + (size_t)(rowBase + ty * 4 + r) * CM + tx * 4) =
            make_float4(acc[r][0], acc[r][1], acc[r][2], acc[r][3]);
    }
}

extern "C" void kernel_launch(void* const* d_in, const int* in_sizes, int n_in,
                              void* d_out, int out_size) {
    const float* m        = (const float*)d_in[0];
    const float* z        = (const float*)d_in[1];
    const float* msa_mask = (const float*)d_in[2];
    const float* z_mask   = (const float*)d_in[3];
    const float* ln_m_g   = (const float*)d_in[4];
    const float* ln_m_b   = (const float*)d_in[5];
    const float* W_v      = (const float*)d_in[6];
    const float* W_g      = (const float*)d_in[7];
    const float* ln_z_g   = (const float*)d_in[8];
    const float* ln_z_b   = (const float*)d_in[9];
    const float* W_b      = (const float*)d_in[10];
    const float* W_o      = (const float*)d_in[11];
    float* out = (float*)d_out;

    const int SMEM_VG  = (128 * 68 + 64 * 132) * 4;   // 68608
    const int SMEM_OUT = (256 * 68 + 256 * 66) * 4;   // 137216
    const int SMEM_EIN = 2 * 15360 * 2;               // 61440
    cudaFuncSetAttribute(k_vg_tc,   cudaFuncAttributeMaxDynamicSharedMemorySize, SMEM_VG);
    cudaFuncSetAttribute(k_out,     cudaFuncAttributeMaxDynamicSharedMemorySize, SMEM_OUT);
    cudaFuncSetAttribute(k_einsum_h,cudaFuncAttributeMaxDynamicSharedMemorySize, SMEM_EIN);

    k_ln_m<<<S_ * I_ / 8, 256>>>(m, ln_m_g, ln_m_b);
    k_vg_tc<<<dim3(4, 1024), 256, SMEM_VG>>>(W_v, W_g, msa_mask);
    k_b<<<I_ * I_ / 8, 256>>>(z, ln_z_g, ln_z_b, W_b, z_mask);
    k_softmax<<<H_ * I_ / 8, 256>>>();
    k_einsum_h<<<dim3(NN / 256, I_ / 128, H_), 256, SMEM_EIN>>>();
    k_out<<<S_ * I_ / 64, 256, SMEM_OUT>>>(W_o, out);
}